// round 15
// baseline (speedup 1.0000x reference)
#include <cuda_runtime.h>

#define BSZ 512
#define DIM 65536
#define NTP 1024
#define NTM 512
#define TILE 16384
#define USTAGE_U64 (56 * 8)
#define SMEM_BYTES (TILE * 8 + USTAGE_U64 * 8)

__device__ float2 g_psi[(long long)BSZ * DIM];   // 256 MB scratch statevector
__device__ float  g_norminv[BSZ];
__device__ float2 g_Upk[56][8];                  // packed f32x2 unitary constants
__device__ float  g_part[BSZ * 4 * 32];

__device__ __forceinline__ int sw(int l) { return l ^ ((l >> 4) & 15); }

typedef unsigned long long u64;
__device__ __forceinline__ u64 f2mul(u64 a, u64 b) {
  u64 d; asm("mul.rn.f32x2 %0,%1,%2;" : "=l"(d) : "l"(a), "l"(b)); return d;
}
__device__ __forceinline__ u64 f2fma(u64 a, u64 b, u64 c) {
  u64 d; asm("fma.rn.f32x2 %0,%1,%2,%3;" : "=l"(d) : "l"(a), "l"(b), "l"(c)); return d;
}
__device__ __forceinline__ u64 swp(u64 a) { return (a >> 32) | (a << 32); }

// ---- 2x2 complex helpers (setup only) ----
struct C2 { float2 a, b, c, d; };
__device__ __forceinline__ float2 cmul(float2 x, float2 y) {
  return make_float2(x.x * y.x - x.y * y.y, x.x * y.y + x.y * y.x);
}
__device__ __forceinline__ float2 cad(float2 x, float2 y) { return make_float2(x.x + y.x, x.y + y.y); }
__device__ C2 mmul(C2 X, C2 Y) {   // X*Y (Y applied first)
  C2 r;
  r.a = cad(cmul(X.a, Y.a), cmul(X.b, Y.c));
  r.b = cad(cmul(X.a, Y.b), cmul(X.b, Y.d));
  r.c = cad(cmul(X.c, Y.a), cmul(X.d, Y.c));
  r.d = cad(cmul(X.c, Y.b), cmul(X.d, Y.d));
  return r;
}

// Setup: composite unitary table, stored pre-broadcast/pre-negated for f32x2.
__global__ void kSetup(const float* ra, const float* trx, const float* try_) {
  if (threadIdx.x) return;
  float2 tg[24];
  for (int i = 0; i < 24; i++) {
    float a = (i < 20) ? ra[i] : (i < 22 ? trx[i - 20] : try_[i - 22]);
    tg[i] = make_float2(cosf(a * 0.5f), sinf(a * 0.5f));
  }
#define MRX(i) C2{make_float2(tg[i].x,0.f), make_float2(0.f,-tg[i].y), make_float2(0.f,-tg[i].y), make_float2(tg[i].x,0.f)}
#define MRY(i) C2{make_float2(tg[i].x,0.f), make_float2(-tg[i].y,0.f), make_float2(tg[i].y,0.f), make_float2(tg[i].x,0.f)}
  C2 M[56];
  M[0] = mmul(MRY(19), MRX(3));
  M[1] = MRX(6);  M[2] = MRX(9);  M[3] = MRX(12);
  M[4] = MRY(1);  M[5] = MRY(4);  M[6] = MRY(7);  M[7] = MRY(10);
  M[8] = MRX(15); M[9] = MRX(18);
  for (int k = 10; k <= 21; k++) M[k] = MRX(20);
  M[22] = mmul(MRX(20), MRY(13));
  M[23] = mmul(MRX(20), mmul(MRY(16), MRX(0)));
  M[24] = MRX(20); M[25] = MRX(20);
  for (int k = 26; k <= 38; k++) M[k] = MRY(22);
  for (int k = 39; k <= 49; k++) M[k] = MRX(21);
  M[50] = mmul(MRX(21), MRY(22));
  M[51] = M[50]; M[52] = M[50];
  M[53] = MRX(21); M[54] = MRX(21);
  for (int k = 0; k < 55; k++) {
    float2 e[4] = {M[k].a, M[k].b, M[k].c, M[k].d};
    for (int i = 0; i < 4; i++) {
      g_Upk[k][2 * i]     = make_float2(e[i].x, e[i].x);    // broadcast real
      g_Upk[k][2 * i + 1] = make_float2(-e[i].y, e[i].y);   // (-imag, +imag)
    }
  }
}

// Stage the packed unitary table into shared memory (Us = t + TILE region).
template<int NTT>
__device__ __forceinline__ void stageU(u64* Us) {
  const u64* src = (const u64*)g_Upk;
  for (int i = threadIdx.x; i < USTAGE_U64; i += NTT) Us[i] = src[i];
}

// ---- f32x2 static sweep; unitary constants pulled from smem per wire ----
template<int NTT, int NW, int M0, int M1, int M2, int M3>
__device__ __forceinline__ void usweepF(float2* t, const u64* Us, int ubase) {
  constexpr int NA = 1 << NW;
  constexpr int ITERS = (TILE >> NW) / NTT;
  __syncthreads();
#pragma unroll
  for (int it = 0; it < ITERS; it++) {
    int q = threadIdx.x + it * NTT;
    int idx = q;
    idx = ((idx & ~(M0 - 1)) << 1) | (idx & (M0 - 1));
    if (NW > 1) idx = ((idx & ~(M1 - 1)) << 1) | (idx & (M1 - 1));
    if (NW > 2) idx = ((idx & ~(M2 - 1)) << 1) | (idx & (M2 - 1));
    if (NW > 3) idx = ((idx & ~(M3 - 1)) << 1) | (idx & (M3 - 1));
    const int MS[4] = {M0, M1, M2, M3};
    u64 v[NA];
#pragma unroll
    for (int j = 0; j < NA; j++) {
      int off = 0;
#pragma unroll
      for (int k = 0; k < NW; k++) if ((j >> k) & 1) off |= MS[k];
      v[j] = *(const u64*)&t[sw(idx | off)];
    }
#pragma unroll
    for (int k = 0; k < NW; k++) {
      const u64* Uk = Us + (ubase + k) * 8;
      u64 u0 = Uk[0], u1 = Uk[1], u2 = Uk[2], u3 = Uk[3];
      u64 u4 = Uk[4], u5 = Uk[5], u6 = Uk[6], u7 = Uk[7];
#pragma unroll
      for (int j = 0; j < NA; j++) if (!((j >> k) & 1)) {
        u64 A = v[j], B = v[j | (1 << k)];
        u64 As = swp(A), Bs = swp(B);
        u64 nA = f2mul(u0, A);
        nA = f2fma(u1, As, nA);
        nA = f2fma(u2, B, nA);
        nA = f2fma(u3, Bs, nA);
        u64 nB = f2mul(u4, A);
        nB = f2fma(u5, As, nB);
        nB = f2fma(u6, B, nB);
        nB = f2fma(u7, Bs, nB);
        v[j] = nA; v[j | (1 << k)] = nB;
      }
    }
#pragma unroll
    for (int j = 0; j < NA; j++) {
      int off = 0;
#pragma unroll
      for (int k = 0; k < NW; k++) if ((j >> k) & 1) off |= MS[k];
      *(u64*)&t[sw(idx | off)] = v[j];
    }
  }
}

// CNOT-chain permutation sweep.
template<bool ASC, int NTT>
__device__ __forceinline__ void permchain(float2* t) {
  __syncthreads();
  constexpr int PER = TILE / NTT;
  float2 v[PER];
  int d0 = threadIdx.x * PER;
#pragma unroll
  for (int j = 0; j < PER; j++) {
    int d = d0 + j, src;
    if (ASC) {
      src = d;
#pragma unroll
      for (int k = 9; k >= 4; k--) src ^= (src >> 1) & (1 << k);
    } else {
      src = d ^ ((d >> 1) & 0x0FFF);
    }
    v[j] = t[sw(src)];
  }
  __syncthreads();
#pragma unroll
  for (int j = 0; j < PER; j++) t[sw(d0 + j)] = v[j];
}

// ---- global <-> smem tile movement (smem swizzled) ----
__device__ __forceinline__ void loadA(float2* t, int b, int o) {
  const float4* gp = (const float4*)(g_psi + (long long)b * DIM + o * TILE);
  for (int k = threadIdx.x; k < TILE / 2; k += blockDim.x) {
    float4 w4 = gp[k];
    t[sw(2 * k)]     = make_float2(w4.x, w4.y);
    t[sw(2 * k + 1)] = make_float2(w4.z, w4.w);
  }
}
__device__ __forceinline__ void storeA(const float2* t, int b, int o) {
  float4* gp = (float4*)(g_psi + (long long)b * DIM + o * TILE);
  for (int k = threadIdx.x; k < TILE / 2; k += blockDim.x) {
    float2 a = t[sw(2 * k)], c = t[sw(2 * k + 1)];
    gp[k] = make_float4(a.x, a.y, c.x, c.y);
  }
}
__device__ __forceinline__ void loadB(float2* t, int b, int o, int lead) {
  const float2* base = g_psi + (long long)b * DIM + (o << 10);
  for (int k = threadIdx.x; k < TILE / 2; k += blockDim.x) {
    int s = 2 * k;
    int r = s >> 10, lo = s & 1023;
    float4 w4 = *(const float4*)(base + (r << 12) + lo);
    t[sw(s)] = make_float2(w4.x, w4.y);
    int d1 = (s + 1) ^ (lead << 13);
    t[sw(d1)] = make_float2(w4.z, w4.w);
  }
}
__device__ __forceinline__ void storeB(const float2* t, int b, int o, int foldmask) {
  float2* base = g_psi + (long long)b * DIM + (o << 10);
  for (int k = threadIdx.x; k < TILE / 2; k += blockDim.x) {
    int d = 2 * k;
    int src = d ^ ((d >> 1) & foldmask);
    float2 a = t[sw(src)], c = t[sw(src + 1)];
    int r = d >> 10, lo = d & 1023;
    *(float4*)(base + (r << 12) + lo) = make_float4(a.x, a.y, c.x, c.y);
  }
}

// ---- kernels ----
__global__ void __launch_bounds__(256) kNorm(const float* states) {
  __shared__ float red[256];
  int b = blockIdx.x;
  const float4* p = (const float4*)(states + (long long)b * DIM);
  float s = 0.f;
  for (int k = threadIdx.x; k < DIM / 4; k += 256) {
    float4 v = p[k];
    s += v.x * v.x + v.y * v.y + v.z * v.z + v.w * v.w;
  }
  red[threadIdx.x] = s;
  __syncthreads();
  for (int off = 128; off; off >>= 1) {
    if (threadIdx.x < off) red[threadIdx.x] += red[threadIdx.x + off];
    __syncthreads();
  }
  if (threadIdx.x == 0) g_norminv[b] = rsqrtf(red[0]);
}

__global__ void __launch_bounds__(NTP) kP1(const float* states) {
  extern __shared__ float2 t[];
  u64* Us = (u64*)(t + TILE);
  int b = blockIdx.x >> 2, o = blockIdx.x & 3;
  float ninv = g_norminv[b];
  const float4* gp = (const float4*)(states + (long long)b * DIM + o * TILE);
  for (int k = threadIdx.x; k < TILE / 4; k += NTP) {
    float4 v = gp[k];
    int i = 4 * k;
    t[sw(i + 0)] = make_float2(v.x * ninv, 0.f);
    t[sw(i + 1)] = make_float2(v.y * ninv, 0.f);
    t[sw(i + 2)] = make_float2(v.z * ninv, 0.f);
    t[sw(i + 3)] = make_float2(v.w * ninv, 0.f);
  }
  stageU<NTP>(Us);
  usweepF<NTP, 4, 1, 2, 4, 8>(t, Us, 0);
  usweepF<NTP, 4, 1024, 2048, 4096, 8192>(t, Us, 4);
  permchain<true, NTP>(t);
  usweepF<NTP, 2, 16, 32, 64, 128>(t, Us, 8);
  __syncthreads();
  storeA(t, b, o);
}

__global__ void __launch_bounds__(NTP) kP2() {
  extern __shared__ float2 t[];
  u64* Us = (u64*)(t + TILE);
  int b = blockIdx.x >> 2, o = blockIdx.x & 3;
  loadB(t, b, o, 0);
  stageU<NTP>(Us);
  usweepF<NTP, 4, 1, 2, 4, 8>(t, Us, 10);
  usweepF<NTP, 4, 16, 32, 64, 128>(t, Us, 14);
  usweepF<NTP, 4, 256, 512, 1024, 2048>(t, Us, 18);
  usweepF<NTP, 2, 4096, 8192, 0x4000, 0x8000>(t, Us, 22);
  __syncthreads();
  storeB(t, b, o, 0x1C00);
}

__global__ void __launch_bounds__(NTP) kP3() {
  extern __shared__ float2 t[];
  u64* Us = (u64*)(t + TILE);
  int b = blockIdx.x >> 2, o = blockIdx.x & 3;
  loadA(t, b, o);
  stageU<NTP>(Us);
  usweepF<NTP, 2, 1024, 2048, 0x4000, 0x8000>(t, Us, 24);
  permchain<false, NTP>(t);
  usweepF<NTP, 4, 2, 4, 8, 16>(t, Us, 26);
  usweepF<NTP, 4, 32, 64, 128, 256>(t, Us, 30);
  usweepF<NTP, 4, 512, 1024, 2048, 4096>(t, Us, 34);
  usweepF<NTP, 1, 8192, 0x4000, 0x8000, 0x10000>(t, Us, 38);
  __syncthreads();
  storeA(t, b, o);
}

__global__ void __launch_bounds__(NTP) kP4() {
  extern __shared__ float2 t[];
  u64* Us = (u64*)(t + TILE);
  int b = blockIdx.x >> 2, o = blockIdx.x & 3;
  loadB(t, b, o, 1);
  stageU<NTP>(Us);
  usweepF<NTP, 4, 2, 4, 8, 16>(t, Us, 39);
  usweepF<NTP, 4, 32, 64, 128, 256>(t, Us, 43);
  usweepF<NTP, 4, 512, 1024, 2048, 4096>(t, Us, 47);
  usweepF<NTP, 2, 1, 8192, 0x4000, 0x8000>(t, Us, 51);
  __syncthreads();
  storeB(t, b, o, 0x1C00);
}

// Measure: cross-tile X (pre-P5, commutes), P5 in smem, Z + grouped in-tile X.
__global__ void __launch_bounds__(NTM) kMeasure() {
  extern __shared__ float2 t[];
  u64* Us = (u64*)(t + TILE);
  int b = blockIdx.x >> 2, o = blockIdx.x & 3;
  loadA(t, b, o);
  stageU<NTM>(Us);
  __syncthreads();

  float zacc[16], xacc[16];
#pragma unroll
  for (int w = 0; w < 16; ++w) { zacc[w] = 0.f; xacc[w] = 0.f; }

  const float2* base = g_psi + (long long)b * DIM;
  if (o < 2) {      // bit15==0: Xop_0 = X_b15 ; Xop_15 = X_b15 X_b0
    float a0 = 0.f, a15 = 0.f;
    for (int l = threadIdx.x; l < TILE; l += NTM) {
      int i = (o << 14) | l;
      float2 a = t[sw(l)];
      float2 p0 = base[i | 0x8000];
      float2 p1 = base[(i | 0x8000) ^ 1];
      a0 += a.x * p0.x + a.y * p0.y;
      a15 += a.x * p1.x + a.y * p1.y;
    }
    xacc[0] = 2.f * a0;
    xacc[15] = 2.f * a15;
  }
  if ((o & 1) == 0) {  // bit14==0: Xop_1 = X_b14
    float a1 = 0.f;
    for (int l = threadIdx.x; l < TILE; l += NTM) {
      int i = (o << 14) | l;
      float2 a = t[sw(l)];
      float2 p = base[i | 0x4000];
      a1 += a.x * p.x + a.y * p.y;
    }
    xacc[1] = 2.f * a1;
  }

  // P5: RX b10,b11 + 12-CNOT ladder (usweepF has leading sync)
  usweepF<NTM, 2, 1024, 2048, 0x4000, 0x8000>(t, Us, 53);
  permchain<false, NTM>(t);
  __syncthreads();

  // Pass A: bits {1..4} -> X for w=14..11, Z fused (full-tile read)
  for (int q = threadIdx.x; q < TILE / 16; q += NTM) {
    int idx = (q & 1) | ((q & ~1) << 4);
    float2 v[16];
#pragma unroll
    for (int j = 0; j < 16; j++) v[j] = t[sw(idx | (j << 1))];
#pragma unroll
    for (int j = 0; j < 16; j++) {
      float2 a = v[j];
      float p = a.x * a.x + a.y * a.y;
      int i = (o << 14) | idx | (j << 1);
      zacc[0] += (((i >> 15) ^ i) & 1) ? -p : p;
#pragma unroll
      for (int w = 1; w < 16; ++w)
        zacc[w] += ((i >> (15 - w)) & 1) ? -p : p;
    }
#pragma unroll
    for (int k = 0; k < 4; k++) {
      float acc = 0.f;
#pragma unroll
      for (int j = 0; j < 16; j++) if (!((j >> k) & 1)) {
        float2 a = v[j], c = v[j | (1 << k)];
        acc += a.x * c.x + a.y * c.y;
      }
      xacc[14 - k] += 2.f * acc;
    }
  }
  // Pass B: bits {5..8} -> X for w=10..7
  for (int q = threadIdx.x; q < TILE / 16; q += NTM) {
    int idx = (q & 31) | ((q & ~31) << 4);
    float2 v[16];
#pragma unroll
    for (int j = 0; j < 16; j++) v[j] = t[sw(idx | (j << 5))];
#pragma unroll
    for (int k = 0; k < 4; k++) {
      float acc = 0.f;
#pragma unroll
      for (int j = 0; j < 16; j++) if (!((j >> k) & 1)) {
        float2 a = v[j], c = v[j | (1 << k)];
        acc += a.x * c.x + a.y * c.y;
      }
      xacc[10 - k] += 2.f * acc;
    }
  }
  // Pass C: bits {9..12} -> X for w=6..3
  for (int q = threadIdx.x; q < TILE / 16; q += NTM) {
    int idx = (q & 511) | ((q & ~511) << 4);
    float2 v[16];
#pragma unroll
    for (int j = 0; j < 16; j++) v[j] = t[sw(idx | (j << 9))];
#pragma unroll
    for (int k = 0; k < 4; k++) {
      float acc = 0.f;
#pragma unroll
      for (int j = 0; j < 16; j++) if (!((j >> k) & 1)) {
        float2 a = v[j], c = v[j | (1 << k)];
        acc += a.x * c.x + a.y * c.y;
      }
      xacc[6 - k] += 2.f * acc;
    }
  }
  // Pass D: mask 8192 -> w=2
  {
    float acc = 0.f;
    for (int q = threadIdx.x; q < TILE / 2; q += NTM) {
      float2 a = t[sw(q)], c = t[sw(q | 8192)];
      acc += a.x * c.x + a.y * c.y;
    }
    xacc[2] = 2.f * acc;
  }

  __syncthreads();
  float* red = (float*)t;
  int lane = threadIdx.x & 31, wid = threadIdx.x >> 5;
#pragma unroll
  for (int v = 0; v < 32; ++v) {
    float val = (v < 16) ? zacc[v] : xacc[v - 16];
#pragma unroll
    for (int off = 16; off; off >>= 1) val += __shfl_down_sync(0xffffffffu, val, off);
    if (lane == 0) red[wid * 32 + v] = val;
  }
  __syncthreads();
  if (threadIdx.x < 32) {
    int v = threadIdx.x;
    float s = 0.f;
    for (int w = 0; w < NTM / 32; ++w) s += red[w * 32 + v];
    g_part[blockIdx.x * 32 + v] = s;
  }
}

__global__ void __launch_bounds__(128) kHead(
    const float* theta_ry, const float* w1, const float* b1,
    const float* w2, const float* b2, const float* g1, const float* be1,
    const float* g2, const float* be2, const float* wh, const float* bh,
    float* out) {
  int b = blockIdx.x * blockDim.x + threadIdx.x;
  if (b >= BSZ) return;

  float attn[16], xs[16];
#pragma unroll
  for (int w = 0; w < 16; ++w) {
    float za = 0.f, xa = 0.f;
#pragma unroll
    for (int o = 0; o < 4; ++o) {
      za += g_part[(b * 4 + o) * 32 + w];
      xa += g_part[(b * 4 + o) * 32 + 16 + w];
    }
    attn[w] = za; xs[w] = xa;
  }
  float th = theta_ry[1];
  float cb = cosf(th), sb = sinf(th);
  float m[16];
#pragma unroll
  for (int w = 0; w < 16; ++w) m[w] = cb * attn[w] - sb * xs[w];

  float mu = 0.f;
#pragma unroll
  for (int w = 0; w < 16; ++w) mu += attn[w];
  mu *= (1.f / 16.f);
  float var = 0.f;
#pragma unroll
  for (int w = 0; w < 16; ++w) { float d = attn[w] - mu; var += d * d; }
  var *= (1.f / 16.f);
  float rs = rsqrtf(var + 1e-5f);
  float x[16];
#pragma unroll
  for (int w = 0; w < 16; ++w) x[w] = (attn[w] - mu) * rs * g1[16 + w] + be1[16 + w];

  float ffn[16];
#pragma unroll
  for (int w = 0; w < 16; ++w) ffn[w] = b2[16 + w];
  for (int j = 0; j < 64; ++j) {
    float h = b1[64 + j];
#pragma unroll
    for (int w = 0; w < 16; ++w) h += m[w] * w1[1024 + j * 16 + w];
    h = fmaxf(h, 0.f);
#pragma unroll
    for (int w = 0; w < 16; ++w) ffn[w] += h * w2[1024 + w * 64 + j];
  }

  float y[16];
#pragma unroll
  for (int w = 0; w < 16; ++w) y[w] = x[w] + ffn[w];
  float mu2 = 0.f;
#pragma unroll
  for (int w = 0; w < 16; ++w) mu2 += y[w];
  mu2 *= (1.f / 16.f);
  float var2 = 0.f;
#pragma unroll
  for (int w = 0; w < 16; ++w) { float d = y[w] - mu2; var2 += d * d; }
  var2 *= (1.f / 16.f);
  float rs2 = rsqrtf(var2 + 1e-5f);

  float ov = bh[0];
#pragma unroll
  for (int w = 0; w < 16; ++w)
    ov += ((y[w] - mu2) * rs2 * g2[16 + w] + be2[16 + w]) * wh[w];
  out[b] = ov;
}

extern "C" void kernel_launch(void* const* d_in, const int* in_sizes, int n_in,
                              void* d_out, int out_size) {
  const float* states = (const float*)d_in[0];
  const float* ra     = (const float*)d_in[1];
  const float* trx    = (const float*)d_in[2];
  const float* try_   = (const float*)d_in[3];
  const float* w1     = (const float*)d_in[4];
  const float* b1     = (const float*)d_in[5];
  const float* w2     = (const float*)d_in[6];
  const float* b2     = (const float*)d_in[7];
  const float* g1     = (const float*)d_in[8];
  const float* be1    = (const float*)d_in[9];
  const float* g2     = (const float*)d_in[10];
  const float* be2    = (const float*)d_in[11];
  const float* wh     = (const float*)d_in[12];
  const float* bh     = (const float*)d_in[13];
  float* out = (float*)d_out;

  cudaFuncSetAttribute(kP1, cudaFuncAttributeMaxDynamicSharedMemorySize, SMEM_BYTES);
  cudaFuncSetAttribute(kP2, cudaFuncAttributeMaxDynamicSharedMemorySize, SMEM_BYTES);
  cudaFuncSetAttribute(kP3, cudaFuncAttributeMaxDynamicSharedMemorySize, SMEM_BYTES);
  cudaFuncSetAttribute(kP4, cudaFuncAttributeMaxDynamicSharedMemorySize, SMEM_BYTES);
  cudaFuncSetAttribute(kMeasure, cudaFuncAttributeMaxDynamicSharedMemorySize, SMEM_BYTES);

  kSetup<<<1, 32>>>(ra, trx, try_);
  kNorm<<<BSZ, 256>>>(states);
  kP1<<<BSZ * 4, NTP, SMEM_BYTES>>>(states);
  kP2<<<BSZ * 4, NTP, SMEM_BYTES>>>();
  kP3<<<BSZ * 4, NTP, SMEM_BYTES>>>();
  kP4<<<BSZ * 4, NTP, SMEM_BYTES>>>();
  kMeasure<<<BSZ * 4, NTM, SMEM_BYTES>>>();
  kHead<<<(BSZ + 127) / 128, 128>>>(try_, w1, b1, w2, b2, g1, be1, g2, be2, wh, bh, out);
}

// round 16
// speedup vs baseline: 1.2398x; 1.2398x over previous
#include <cuda_runtime.h>

#define BSZ 512
#define DIM 65536
#define NTP 512
#define NTM 512
#define TILE 16384
#define SMEM_BYTES (TILE * 8)

__device__ float2 g_psi[(long long)BSZ * DIM];   // 256 MB scratch statevector
__device__ float  g_norminv[BSZ];
__device__ float2 g_Upk[56][8];                  // packed f32x2 unitary constants
__device__ float  g_part[BSZ * 4 * 32];

__device__ __forceinline__ int sw(int l) { return l ^ ((l >> 4) & 15); }

typedef unsigned long long u64;
__device__ __forceinline__ u64 f2mul(u64 a, u64 b) {
  u64 d; asm("mul.rn.f32x2 %0,%1,%2;" : "=l"(d) : "l"(a), "l"(b)); return d;
}
__device__ __forceinline__ u64 f2fma(u64 a, u64 b, u64 c) {
  u64 d; asm("fma.rn.f32x2 %0,%1,%2,%3;" : "=l"(d) : "l"(a), "l"(b), "l"(c)); return d;
}
__device__ __forceinline__ u64 f2add(u64 a, u64 b) {
  u64 d; asm("add.rn.f32x2 %0,%1,%2;" : "=l"(d) : "l"(a), "l"(b)); return d;
}
__device__ __forceinline__ u64 f2sub(u64 a, u64 b) {
  return f2fma(0xBF800000BF800000ULL, b, a);   // a + (-1)*b, single rounding
}
__device__ __forceinline__ u64 swp(u64 a) { return (a >> 32) | (a << 32); }
__device__ __forceinline__ float lsum(u64 a) { float2 f = *(float2*)&a; return f.x + f.y; }

// ---- 2x2 complex helpers (setup only) ----
struct C2 { float2 a, b, c, d; };
__device__ __forceinline__ float2 cmul(float2 x, float2 y) {
  return make_float2(x.x * y.x - x.y * y.y, x.x * y.y + x.y * y.x);
}
__device__ __forceinline__ float2 cad(float2 x, float2 y) { return make_float2(x.x + y.x, x.y + y.y); }
__device__ C2 mmul(C2 X, C2 Y) {   // X*Y (Y applied first)
  C2 r;
  r.a = cad(cmul(X.a, Y.a), cmul(X.b, Y.c));
  r.b = cad(cmul(X.a, Y.b), cmul(X.b, Y.d));
  r.c = cad(cmul(X.c, Y.a), cmul(X.d, Y.c));
  r.d = cad(cmul(X.c, Y.b), cmul(X.d, Y.d));
  return r;
}

// Setup: composite unitary table. Per-slot packing depends on gate type:
//  RX: [0]=(c,c) [1]=(s,-s);  RY: [0]=(c,c) [1]=(-s,-s) [2]=(s,s);  GEN: 8 entries.
__global__ void kSetup(const float* ra, const float* trx, const float* try_) {
  if (threadIdx.x) return;
  float2 tg[24];
  for (int i = 0; i < 24; i++) {
    float a = (i < 20) ? ra[i] : (i < 22 ? trx[i - 20] : try_[i - 22]);
    tg[i] = make_float2(cosf(a * 0.5f), sinf(a * 0.5f));
  }
#define MRX(i) C2{make_float2(tg[i].x,0.f), make_float2(0.f,-tg[i].y), make_float2(0.f,-tg[i].y), make_float2(tg[i].x,0.f)}
#define MRY(i) C2{make_float2(tg[i].x,0.f), make_float2(-tg[i].y,0.f), make_float2(tg[i].y,0.f), make_float2(tg[i].x,0.f)}
  C2 M[56];
  M[0] = mmul(MRY(19), MRX(3));
  M[1] = MRX(6);  M[2] = MRX(9);  M[3] = MRX(12);
  M[4] = MRY(1);  M[5] = MRY(4);  M[6] = MRY(7);  M[7] = MRY(10);
  M[8] = MRX(15); M[9] = MRX(18);
  for (int k = 10; k <= 21; k++) M[k] = MRX(20);
  M[22] = mmul(MRX(20), MRY(13));
  M[23] = mmul(MRX(20), mmul(MRY(16), MRX(0)));
  M[24] = MRX(20); M[25] = MRX(20);
  for (int k = 26; k <= 38; k++) M[k] = MRY(22);
  for (int k = 39; k <= 49; k++) M[k] = MRX(21);
  M[50] = mmul(MRX(21), MRY(22));
  M[51] = M[50]; M[52] = M[50];
  M[53] = MRX(21); M[54] = MRX(21);
  for (int k = 0; k < 55; k++) {
    int typ = 0;                                    // RX
    if (k == 0 || k == 22 || k == 23 || (k >= 50 && k <= 52)) typ = 2;  // GEN
    else if ((k >= 4 && k <= 7) || (k >= 26 && k <= 38)) typ = 1;       // RY
    float2 e[4] = {M[k].a, M[k].b, M[k].c, M[k].d};
    if (typ == 2) {
      for (int i = 0; i < 4; i++) {
        g_Upk[k][2 * i]     = make_float2(e[i].x, e[i].x);
        g_Upk[k][2 * i + 1] = make_float2(-e[i].y, e[i].y);
      }
    } else if (typ == 0) {
      float c = e[0].x, s = -e[1].y;
      g_Upk[k][0] = make_float2(c, c);
      g_Upk[k][1] = make_float2(s, -s);
    } else {
      float c = e[0].x, s = e[2].x;
      g_Upk[k][0] = make_float2(c, c);
      g_Upk[k][1] = make_float2(-s, -s);
      g_Upk[k][2] = make_float2(s, s);
    }
  }
}

// Apply one wire (local reg-bit K) of type T (0=RX,1=RY,2=GEN) to NA amplitudes.
template<int NA, int K, int T>
__device__ __forceinline__ void wireOp(u64* v, const float2* Ug) {
  const u64* U = (const u64*)Ug;
  if (T == 0) {           // RX: nA = c*A + (s,-s)*swap(B); nB = c*B + (s,-s)*swap(A)
    u64 c = U[0], s = U[1];
#pragma unroll
    for (int j = 0; j < NA; j++) if (!((j >> K) & 1)) {
      u64 A = v[j], B = v[j | (1 << K)];
      v[j]            = f2fma(s, swp(B), f2mul(c, A));
      v[j | (1 << K)] = f2fma(s, swp(A), f2mul(c, B));
    }
  } else if (T == 1) {    // RY: nA = c*A - s*B; nB = s*A + c*B
    u64 c = U[0], ns = U[1], s = U[2];
#pragma unroll
    for (int j = 0; j < NA; j++) if (!((j >> K) & 1)) {
      u64 A = v[j], B = v[j | (1 << K)];
      v[j]            = f2fma(ns, B, f2mul(c, A));
      v[j | (1 << K)] = f2fma(c, B, f2mul(s, A));
    }
  } else {                // general complex 2x2
    u64 u0 = U[0], u1 = U[1], u2 = U[2], u3 = U[3];
    u64 u4 = U[4], u5 = U[5], u6 = U[6], u7 = U[7];
#pragma unroll
    for (int j = 0; j < NA; j++) if (!((j >> K) & 1)) {
      u64 A = v[j], B = v[j | (1 << K)];
      u64 As = swp(A), Bs = swp(B);
      u64 nA = f2mul(u0, A);
      nA = f2fma(u1, As, nA); nA = f2fma(u2, B, nA); nA = f2fma(u3, Bs, nA);
      u64 nB = f2mul(u4, A);
      nB = f2fma(u5, As, nB); nB = f2fma(u6, B, nB); nB = f2fma(u7, Bs, nB);
      v[j] = nA; v[j | (1 << K)] = nB;
    }
  }
}

// Typed static sweep: NW wires on compile-time masks (ascending), types T0..T3.
template<int NTT, int NW, int M0, int M1, int M2, int M3, int T0, int T1, int T2, int T3>
__device__ __forceinline__ void usweepT(float2* t, int ubase) {
  constexpr int NA = 1 << NW;
  constexpr int ITERS = (TILE >> NW) / NTT;
  __syncthreads();
#pragma unroll
  for (int it = 0; it < ITERS; it++) {
    int q = threadIdx.x + it * NTT;
    int idx = q;
    idx = ((idx & ~(M0 - 1)) << 1) | (idx & (M0 - 1));
    if (NW > 1) idx = ((idx & ~(M1 - 1)) << 1) | (idx & (M1 - 1));
    if (NW > 2) idx = ((idx & ~(M2 - 1)) << 1) | (idx & (M2 - 1));
    if (NW > 3) idx = ((idx & ~(M3 - 1)) << 1) | (idx & (M3 - 1));
    const int MS[4] = {M0, M1, M2, M3};
    u64 v[NA];
#pragma unroll
    for (int j = 0; j < NA; j++) {
      int off = 0;
#pragma unroll
      for (int k = 0; k < 4; k++) if (k < NW && ((j >> k) & 1)) off |= MS[k];
      v[j] = *(const u64*)&t[sw(idx | off)];
    }
    wireOp<NA, 0, T0>(v, g_Upk[ubase + 0]);
    if (NW > 1) wireOp<NA, 1, T1>(v, g_Upk[ubase + 1]);
    if (NW > 2) wireOp<NA, 2, T2>(v, g_Upk[ubase + 2]);
    if (NW > 3) wireOp<NA, 3, T3>(v, g_Upk[ubase + 3]);
#pragma unroll
    for (int j = 0; j < NA; j++) {
      int off = 0;
#pragma unroll
      for (int k = 0; k < 4; k++) if (k < NW && ((j >> k) & 1)) off |= MS[k];
      *(u64*)&t[sw(idx | off)] = v[j];
    }
  }
}

// CNOT-chain permutation sweep.
template<bool ASC, int NTT>
__device__ __forceinline__ void permchain(float2* t) {
  __syncthreads();
  constexpr int PER = TILE / NTT;
  float2 v[PER];
  int d0 = threadIdx.x * PER;
#pragma unroll
  for (int j = 0; j < PER; j++) {
    int d = d0 + j, src;
    if (ASC) {
      src = d;
#pragma unroll
      for (int k = 9; k >= 4; k--) src ^= (src >> 1) & (1 << k);
    } else {
      src = d ^ ((d >> 1) & 0x0FFF);
    }
    v[j] = t[sw(src)];
  }
  __syncthreads();
#pragma unroll
  for (int j = 0; j < PER; j++) t[sw(d0 + j)] = v[j];
}

// ---- global <-> smem tile movement (smem swizzled) ----
__device__ __forceinline__ void loadA(float2* t, int b, int o) {
  const float4* gp = (const float4*)(g_psi + (long long)b * DIM + o * TILE);
  for (int k = threadIdx.x; k < TILE / 2; k += blockDim.x) {
    float4 w4 = gp[k];
    t[sw(2 * k)]     = make_float2(w4.x, w4.y);
    t[sw(2 * k + 1)] = make_float2(w4.z, w4.w);
  }
}
__device__ __forceinline__ void storeA(const float2* t, int b, int o) {
  float4* gp = (float4*)(g_psi + (long long)b * DIM + o * TILE);
  for (int k = threadIdx.x; k < TILE / 2; k += blockDim.x) {
    float2 a = t[sw(2 * k)], c = t[sw(2 * k + 1)];
    gp[k] = make_float4(a.x, a.y, c.x, c.y);
  }
}
__device__ __forceinline__ void loadB(float2* t, int b, int o, int lead) {
  const float2* base = g_psi + (long long)b * DIM + (o << 10);
  for (int k = threadIdx.x; k < TILE / 2; k += blockDim.x) {
    int s = 2 * k;
    int r = s >> 10, lo = s & 1023;
    float4 w4 = *(const float4*)(base + (r << 12) + lo);
    t[sw(s)] = make_float2(w4.x, w4.y);
    int d1 = (s + 1) ^ (lead << 13);
    t[sw(d1)] = make_float2(w4.z, w4.w);
  }
}
__device__ __forceinline__ void storeB(const float2* t, int b, int o, int foldmask) {
  float2* base = g_psi + (long long)b * DIM + (o << 10);
  for (int k = threadIdx.x; k < TILE / 2; k += blockDim.x) {
    int d = 2 * k;
    int src = d ^ ((d >> 1) & foldmask);
    float2 a = t[sw(src)], c = t[sw(src + 1)];
    int r = d >> 10, lo = d & 1023;
    *(float4*)(base + (r << 12) + lo) = make_float4(a.x, a.y, c.x, c.y);
  }
}

// ---- kernels ----
__global__ void __launch_bounds__(256) kNorm(const float* states) {
  __shared__ float red[256];
  int b = blockIdx.x;
  const float4* p = (const float4*)(states + (long long)b * DIM);
  float s = 0.f;
  for (int k = threadIdx.x; k < DIM / 4; k += 256) {
    float4 v = p[k];
    s += v.x * v.x + v.y * v.y + v.z * v.z + v.w * v.w;
  }
  red[threadIdx.x] = s;
  __syncthreads();
  for (int off = 128; off; off >>= 1) {
    if (threadIdx.x < off) red[threadIdx.x] += red[threadIdx.x + off];
    __syncthreads();
  }
  if (threadIdx.x == 0) g_norminv[b] = rsqrtf(red[0]);
}

__global__ void __launch_bounds__(NTP) kP1(const float* states) {
  extern __shared__ float2 t[];
  int b = blockIdx.x >> 2, o = blockIdx.x & 3;
  float ninv = g_norminv[b];
  const float4* gp = (const float4*)(states + (long long)b * DIM + o * TILE);
  for (int k = threadIdx.x; k < TILE / 4; k += NTP) {
    float4 v = gp[k];
    int i = 4 * k;
    t[sw(i + 0)] = make_float2(v.x * ninv, 0.f);
    t[sw(i + 1)] = make_float2(v.y * ninv, 0.f);
    t[sw(i + 2)] = make_float2(v.z * ninv, 0.f);
    t[sw(i + 3)] = make_float2(v.w * ninv, 0.f);
  }
  usweepT<NTP, 4, 1, 2, 4, 8,           2, 0, 0, 0>(t, 0);
  usweepT<NTP, 4, 1024, 2048, 4096, 8192, 1, 1, 1, 1>(t, 4);
  permchain<true, NTP>(t);
  usweepT<NTP, 2, 16, 32, 64, 128,      0, 0, 0, 0>(t, 8);
  __syncthreads();
  storeA(t, b, o);
}

__global__ void __launch_bounds__(NTP) kP2() {
  extern __shared__ float2 t[];
  int b = blockIdx.x >> 2, o = blockIdx.x & 3;
  loadB(t, b, o, 0);
  usweepT<NTP, 4, 1, 2, 4, 8,             0, 0, 0, 0>(t, 10);
  usweepT<NTP, 4, 16, 32, 64, 128,        0, 0, 0, 0>(t, 14);
  usweepT<NTP, 4, 256, 512, 1024, 2048,   0, 0, 0, 0>(t, 18);
  usweepT<NTP, 2, 4096, 8192, 0x4000, 0x8000, 2, 2, 0, 0>(t, 22);
  __syncthreads();
  storeB(t, b, o, 0x1C00);
}

__global__ void __launch_bounds__(NTP) kP3() {
  extern __shared__ float2 t[];
  int b = blockIdx.x >> 2, o = blockIdx.x & 3;
  loadA(t, b, o);
  usweepT<NTP, 2, 1024, 2048, 0x4000, 0x8000, 0, 0, 0, 0>(t, 24);
  permchain<false, NTP>(t);
  usweepT<NTP, 4, 2, 4, 8, 16,            1, 1, 1, 1>(t, 26);
  usweepT<NTP, 4, 32, 64, 128, 256,       1, 1, 1, 1>(t, 30);
  usweepT<NTP, 4, 512, 1024, 2048, 4096,  1, 1, 1, 1>(t, 34);
  usweepT<NTP, 1, 8192, 0x4000, 0x8000, 0x10000, 1, 1, 1, 1>(t, 38);
  __syncthreads();
  storeA(t, b, o);
}

__global__ void __launch_bounds__(NTP) kP4() {
  extern __shared__ float2 t[];
  int b = blockIdx.x >> 2, o = blockIdx.x & 3;
  loadB(t, b, o, 1);
  usweepT<NTP, 4, 2, 4, 8, 16,            0, 0, 0, 0>(t, 39);
  usweepT<NTP, 4, 32, 64, 128, 256,       0, 0, 0, 0>(t, 43);
  usweepT<NTP, 4, 512, 1024, 2048, 4096,  0, 0, 0, 2>(t, 47);
  usweepT<NTP, 2, 1, 8192, 0x4000, 0x8000, 2, 2, 0, 0>(t, 51);
  __syncthreads();
  storeB(t, b, o, 0x1C00);
}

// Measure: cross-tile X (pre-P5, commutes), P5 in smem, then WHT-based Z + packed X.
__global__ void __launch_bounds__(NTM) kMeasure() {
  extern __shared__ float2 t[];
  int b = blockIdx.x >> 2, o = blockIdx.x & 3;
  loadA(t, b, o);
  __syncthreads();

  float zacc[16], xacc[16];
#pragma unroll
  for (int w = 0; w < 16; ++w) { zacc[w] = 0.f; xacc[w] = 0.f; }

  const float2* base = g_psi + (long long)b * DIM;
  if (o < 2) {      // bit15==0: Xop_0 = X_b15 ; Xop_15 = X_b15 X_b0
    float a0 = 0.f, a15 = 0.f;
    for (int l = threadIdx.x; l < TILE; l += NTM) {
      int i = (o << 14) | l;
      float2 a = t[sw(l)];
      float2 p0 = base[i | 0x8000];
      float2 p1 = base[(i | 0x8000) ^ 1];
      a0 += a.x * p0.x + a.y * p0.y;
      a15 += a.x * p1.x + a.y * p1.y;
    }
    xacc[0] = 2.f * a0;
    xacc[15] = 2.f * a15;
  }
  if ((o & 1) == 0) {  // bit14==0: Xop_1 = X_b14
    float a1 = 0.f;
    for (int l = threadIdx.x; l < TILE; l += NTM) {
      int i = (o << 14) | l;
      float2 a = t[sw(l)];
      float2 p = base[i | 0x4000];
      a1 += a.x * p.x + a.y * p.y;
    }
    xacc[1] = 2.f * a1;
  }

  // P5: RX b10,b11 + 12-CNOT ladder
  usweepT<NTM, 2, 1024, 2048, 0x4000, 0x8000, 0, 0, 0, 0>(t, 53);
  permchain<false, NTM>(t);
  __syncthreads();

  // Pass A: bits {1..4}. X for w=14..11 + ALL Z via 4-level WHT of |a|^2.
  u64 zD[4] = {0, 0, 0, 0};       // D_k -> zacc[14-k]
  u64 zS1 = 0;                    // unsigned S   -> zacc[1] (block-const sign)
  u64 z15 = 0;                    // bit0-signed  -> zacc[15]; zacc[0] = +/- same
  u64 zB[9] = {0,0,0,0,0,0,0,0,0};// idx-bit-signed -> zacc[2..10]
  u64 xA[4] = {0, 0, 0, 0};
  for (int q = threadIdx.x; q < TILE / 16; q += NTM) {
    int idx = (q & 1) | ((q & ~1) << 4);
    u64 V[16];
#pragma unroll
    for (int j = 0; j < 16; j++) V[j] = *(const u64*)&t[sw(idx | (j << 1))];
#pragma unroll
    for (int k = 0; k < 4; k++)
#pragma unroll
      for (int j = 0; j < 16; j++) if (!((j >> k) & 1))
        xA[k] = f2fma(V[j], V[j | (1 << k)], xA[k]);
    // |a|^2 per lane, then WHT
#pragma unroll
    for (int j = 0; j < 16; j++) V[j] = f2mul(V[j], V[j]);
    u64 A0 = f2add(V[0], V[1]),  B0 = f2sub(V[0], V[1]);
    u64 A1 = f2add(V[2], V[3]),  B1 = f2sub(V[2], V[3]);
    u64 A2 = f2add(V[4], V[5]),  B2 = f2sub(V[4], V[5]);
    u64 A3 = f2add(V[6], V[7]),  B3 = f2sub(V[6], V[7]);
    u64 A4 = f2add(V[8], V[9]),  B4 = f2sub(V[8], V[9]);
    u64 A5 = f2add(V[10], V[11]), B5 = f2sub(V[10], V[11]);
    u64 A6 = f2add(V[12], V[13]), B6 = f2sub(V[12], V[13]);
    u64 A7 = f2add(V[14], V[15]), B7 = f2sub(V[14], V[15]);
    u64 D0 = f2add(f2add(f2add(B0, B1), f2add(B2, B3)),
                   f2add(f2add(B4, B5), f2add(B6, B7)));
    u64 C0 = f2add(A0, A1), E0 = f2sub(A0, A1);
    u64 C1 = f2add(A2, A3), E1 = f2sub(A2, A3);
    u64 C2 = f2add(A4, A5), E2 = f2sub(A4, A5);
    u64 C3 = f2add(A6, A7), E3 = f2sub(A6, A7);
    u64 D1 = f2add(f2add(E0, E1), f2add(E2, E3));
    u64 F0 = f2add(C0, C1), G0 = f2sub(C0, C1);
    u64 F1 = f2add(C2, C3), G1 = f2sub(C2, C3);
    u64 D2 = f2add(G0, G1);
    u64 S  = f2add(F0, F1);
    u64 D3 = f2sub(F0, F1);
    zD[0] = f2add(zD[0], D0); zD[1] = f2add(zD[1], D1);
    zD[2] = f2add(zD[2], D2); zD[3] = f2add(zD[3], D3);
    zS1 = f2add(zS1, S);
    u64 Sn = f2mul(0xBF800000BF800000ULL, S);
    z15 = f2add(z15, (idx & 1) ? Sn : S);
#pragma unroll
    for (int w = 2; w <= 10; w++)
      zB[w - 2] = f2add(zB[w - 2], ((idx >> (15 - w)) & 1) ? Sn : S);
  }
#pragma unroll
  for (int k = 0; k < 4; k++) { zacc[14 - k] = lsum(zD[k]); xacc[14 - k] = 2.f * lsum(xA[k]); }
  zacc[15] = lsum(z15);
  zacc[0]  = ((o >> 1) & 1) ? -zacc[15] : zacc[15];
  zacc[1]  = (o & 1) ? -lsum(zS1) : lsum(zS1);
#pragma unroll
  for (int w = 2; w <= 10; w++) zacc[w] = lsum(zB[w - 2]);

  // Pass B: bits {5..8} -> X for w=10..7
  {
    u64 xB[4] = {0, 0, 0, 0};
    for (int q = threadIdx.x; q < TILE / 16; q += NTM) {
      int idx = (q & 31) | ((q & ~31) << 4);
      u64 V[16];
#pragma unroll
      for (int j = 0; j < 16; j++) V[j] = *(const u64*)&t[sw(idx | (j << 5))];
#pragma unroll
      for (int k = 0; k < 4; k++)
#pragma unroll
        for (int j = 0; j < 16; j++) if (!((j >> k) & 1))
          xB[k] = f2fma(V[j], V[j | (1 << k)], xB[k]);
    }
#pragma unroll
    for (int k = 0; k < 4; k++) xacc[10 - k] = 2.f * lsum(xB[k]);
  }
  // Pass C: bits {9..12} -> X for w=6..3
  {
    u64 xC[4] = {0, 0, 0, 0};
    for (int q = threadIdx.x; q < TILE / 16; q += NTM) {
      int idx = (q & 511) | ((q & ~511) << 4);
      u64 V[16];
#pragma unroll
      for (int j = 0; j < 16; j++) V[j] = *(const u64*)&t[sw(idx | (j << 9))];
#pragma unroll
      for (int k = 0; k < 4; k++)
#pragma unroll
        for (int j = 0; j < 16; j++) if (!((j >> k) & 1))
          xC[k] = f2fma(V[j], V[j | (1 << k)], xC[k]);
    }
#pragma unroll
    for (int k = 0; k < 4; k++) xacc[6 - k] = 2.f * lsum(xC[k]);
  }
  // Pass D: mask 8192 -> w=2
  {
    u64 xD = 0;
    for (int q = threadIdx.x; q < TILE / 2; q += NTM)
      xD = f2fma(*(const u64*)&t[sw(q)], *(const u64*)&t[sw(q | 8192)], xD);
    xacc[2] = 2.f * lsum(xD);
  }

  __syncthreads();
  float* red = (float*)t;
  int lane = threadIdx.x & 31, wid = threadIdx.x >> 5;
#pragma unroll
  for (int v = 0; v < 32; ++v) {
    float val = (v < 16) ? zacc[v] : xacc[v - 16];
#pragma unroll
    for (int off = 16; off; off >>= 1) val += __shfl_down_sync(0xffffffffu, val, off);
    if (lane == 0) red[wid * 32 + v] = val;
  }
  __syncthreads();
  if (threadIdx.x < 32) {
    int v = threadIdx.x;
    float s = 0.f;
    for (int w = 0; w < NTM / 32; ++w) s += red[w * 32 + v];
    g_part[blockIdx.x * 32 + v] = s;
  }
}

__global__ void __launch_bounds__(128) kHead(
    const float* theta_ry, const float* w1, const float* b1,
    const float* w2, const float* b2, const float* g1, const float* be1,
    const float* g2, const float* be2, const float* wh, const float* bh,
    float* out) {
  int b = blockIdx.x * blockDim.x + threadIdx.x;
  if (b >= BSZ) return;

  float attn[16], xs[16];
#pragma unroll
  for (int w = 0; w < 16; ++w) {
    float za = 0.f, xa = 0.f;
#pragma unroll
    for (int o = 0; o < 4; ++o) {
      za += g_part[(b * 4 + o) * 32 + w];
      xa += g_part[(b * 4 + o) * 32 + 16 + w];
    }
    attn[w] = za; xs[w] = xa;
  }
  float th = theta_ry[1];
  float cb = cosf(th), sb = sinf(th);
  float m[16];
#pragma unroll
  for (int w = 0; w < 16; ++w) m[w] = cb * attn[w] - sb * xs[w];

  float mu = 0.f;
#pragma unroll
  for (int w = 0; w < 16; ++w) mu += attn[w];
  mu *= (1.f / 16.f);
  float var = 0.f;
#pragma unroll
  for (int w = 0; w < 16; ++w) { float d = attn[w] - mu; var += d * d; }
  var *= (1.f / 16.f);
  float rs = rsqrtf(var + 1e-5f);
  float x[16];
#pragma unroll
  for (int w = 0; w < 16; ++w) x[w] = (attn[w] - mu) * rs * g1[16 + w] + be1[16 + w];

  float ffn[16];
#pragma unroll
  for (int w = 0; w < 16; ++w) ffn[w] = b2[16 + w];
  for (int j = 0; j < 64; ++j) {
    float h = b1[64 + j];
#pragma unroll
    for (int w = 0; w < 16; ++w) h += m[w] * w1[1024 + j * 16 + w];
    h = fmaxf(h, 0.f);
#pragma unroll
    for (int w = 0; w < 16; ++w) ffn[w] += h * w2[1024 + w * 64 + j];
  }

  float y[16];
#pragma unroll
  for (int w = 0; w < 16; ++w) y[w] = x[w] + ffn[w];
  float mu2 = 0.f;
#pragma unroll
  for (int w = 0; w < 16; ++w) mu2 += y[w];
  mu2 *= (1.f / 16.f);
  float var2 = 0.f;
#pragma unroll
  for (int w = 0; w < 16; ++w) { float d = y[w] - mu2; var2 += d * d; }
  var2 *= (1.f / 16.f);
  float rs2 = rsqrtf(var2 + 1e-5f);

  float ov = bh[0];
#pragma unroll
  for (int w = 0; w < 16; ++w)
    ov += ((y[w] - mu2) * rs2 * g2[16 + w] + be2[16 + w]) * wh[w];
  out[b] = ov;
}

extern "C" void kernel_launch(void* const* d_in, const int* in_sizes, int n_in,
                              void* d_out, int out_size) {
  const float* states = (const float*)d_in[0];
  const float* ra     = (const float*)d_in[1];
  const float* trx    = (const float*)d_in[2];
  const float* try_   = (const float*)d_in[3];
  const float* w1     = (const float*)d_in[4];
  const float* b1     = (const float*)d_in[5];
  const float* w2     = (const float*)d_in[6];
  const float* b2     = (const float*)d_in[7];
  const float* g1     = (const float*)d_in[8];
  const float* be1    = (const float*)d_in[9];
  const float* g2     = (const float*)d_in[10];
  const float* be2    = (const float*)d_in[11];
  const float* wh     = (const float*)d_in[12];
  const float* bh     = (const float*)d_in[13];
  float* out = (float*)d_out;

  cudaFuncSetAttribute(kP1, cudaFuncAttributeMaxDynamicSharedMemorySize, SMEM_BYTES);
  cudaFuncSetAttribute(kP2, cudaFuncAttributeMaxDynamicSharedMemorySize, SMEM_BYTES);
  cudaFuncSetAttribute(kP3, cudaFuncAttributeMaxDynamicSharedMemorySize, SMEM_BYTES);
  cudaFuncSetAttribute(kP4, cudaFuncAttributeMaxDynamicSharedMemorySize, SMEM_BYTES);
  cudaFuncSetAttribute(kMeasure, cudaFuncAttributeMaxDynamicSharedMemorySize, SMEM_BYTES);

  kSetup<<<1, 32>>>(ra, trx, try_);
  kNorm<<<BSZ, 256>>>(states);
  kP1<<<BSZ * 4, NTP, SMEM_BYTES>>>(states);
  kP2<<<BSZ * 4, NTP, SMEM_BYTES>>>();
  kP3<<<BSZ * 4, NTP, SMEM_BYTES>>>();
  kP4<<<BSZ * 4, NTP, SMEM_BYTES>>>();
  kMeasure<<<BSZ * 4, NTM, SMEM_BYTES>>>();
  kHead<<<(BSZ + 127) / 128, 128>>>(try_, w1, b1, w2, b2, g1, be1, g2, be2, wh, bh, out);
}

// round 17
// speedup vs baseline: 1.2603x; 1.0166x over previous
#include <cuda_runtime.h>

#define BSZ 512
#define DIM 65536
#define NTP 1024
#define NTM 512
#define TILE 16384
#define SMEM_BYTES (TILE * 8)

__device__ float2 g_psi[(long long)BSZ * DIM];   // 256 MB scratch statevector
__device__ float  g_norminv[BSZ];
__device__ float2 g_Upk[56][8];                  // packed f32x2 unitary constants
__device__ float  g_part[BSZ * 4 * 32];

__device__ __forceinline__ int sw(int l) { return l ^ ((l >> 4) & 15); }

typedef unsigned long long u64;
__device__ __forceinline__ u64 f2mul(u64 a, u64 b) {
  u64 d; asm("mul.rn.f32x2 %0,%1,%2;" : "=l"(d) : "l"(a), "l"(b)); return d;
}
__device__ __forceinline__ u64 f2fma(u64 a, u64 b, u64 c) {
  u64 d; asm("fma.rn.f32x2 %0,%1,%2,%3;" : "=l"(d) : "l"(a), "l"(b), "l"(c)); return d;
}
__device__ __forceinline__ u64 f2add(u64 a, u64 b) {
  u64 d; asm("add.rn.f32x2 %0,%1,%2;" : "=l"(d) : "l"(a), "l"(b)); return d;
}
__device__ __forceinline__ u64 f2sub(u64 a, u64 b) {
  return f2fma(0xBF800000BF800000ULL, b, a);   // a + (-1)*b, single rounding
}
__device__ __forceinline__ u64 swp(u64 a) { return (a >> 32) | (a << 32); }
__device__ __forceinline__ float lsum(u64 a) { float2 f = *(float2*)&a; return f.x + f.y; }

// ---- 2x2 complex helpers (setup only) ----
struct C2 { float2 a, b, c, d; };
__device__ __forceinline__ float2 cmul(float2 x, float2 y) {
  return make_float2(x.x * y.x - x.y * y.y, x.x * y.y + x.y * y.x);
}
__device__ __forceinline__ float2 cad(float2 x, float2 y) { return make_float2(x.x + y.x, x.y + y.y); }
__device__ C2 mmul(C2 X, C2 Y) {   // X*Y (Y applied first)
  C2 r;
  r.a = cad(cmul(X.a, Y.a), cmul(X.b, Y.c));
  r.b = cad(cmul(X.a, Y.b), cmul(X.b, Y.d));
  r.c = cad(cmul(X.c, Y.a), cmul(X.d, Y.c));
  r.d = cad(cmul(X.c, Y.b), cmul(X.d, Y.d));
  return r;
}

// Setup: composite unitary table. Per-slot packing depends on gate type:
//  RX: [0]=(c,c) [1]=(s,-s);  RY: [0]=(c,c) [1]=(-s,-s) [2]=(s,s);  GEN: 8 entries.
__global__ void kSetup(const float* ra, const float* trx, const float* try_) {
  if (threadIdx.x) return;
  float2 tg[24];
  for (int i = 0; i < 24; i++) {
    float a = (i < 20) ? ra[i] : (i < 22 ? trx[i - 20] : try_[i - 22]);
    tg[i] = make_float2(cosf(a * 0.5f), sinf(a * 0.5f));
  }
#define MRX(i) C2{make_float2(tg[i].x,0.f), make_float2(0.f,-tg[i].y), make_float2(0.f,-tg[i].y), make_float2(tg[i].x,0.f)}
#define MRY(i) C2{make_float2(tg[i].x,0.f), make_float2(-tg[i].y,0.f), make_float2(tg[i].y,0.f), make_float2(tg[i].x,0.f)}
  C2 M[56];
  M[0] = mmul(MRY(19), MRX(3));
  M[1] = MRX(6);  M[2] = MRX(9);  M[3] = MRX(12);
  M[4] = MRY(1);  M[5] = MRY(4);  M[6] = MRY(7);  M[7] = MRY(10);
  M[8] = MRX(15); M[9] = MRX(18);
  for (int k = 10; k <= 21; k++) M[k] = MRX(20);
  M[22] = mmul(MRX(20), MRY(13));
  M[23] = mmul(MRX(20), mmul(MRY(16), MRX(0)));
  M[24] = MRX(20); M[25] = MRX(20);
  for (int k = 26; k <= 38; k++) M[k] = MRY(22);
  for (int k = 39; k <= 49; k++) M[k] = MRX(21);
  M[50] = mmul(MRX(21), MRY(22));
  M[51] = M[50]; M[52] = M[50];
  M[53] = MRX(21); M[54] = MRX(21);
  for (int k = 0; k < 55; k++) {
    int typ = 0;                                    // RX
    if (k == 0 || k == 22 || k == 23 || (k >= 50 && k <= 52)) typ = 2;  // GEN
    else if ((k >= 4 && k <= 7) || (k >= 26 && k <= 38)) typ = 1;       // RY
    float2 e[4] = {M[k].a, M[k].b, M[k].c, M[k].d};
    if (typ == 2) {
      for (int i = 0; i < 4; i++) {
        g_Upk[k][2 * i]     = make_float2(e[i].x, e[i].x);
        g_Upk[k][2 * i + 1] = make_float2(-e[i].y, e[i].y);
      }
    } else if (typ == 0) {
      float c = e[0].x, s = -e[1].y;
      g_Upk[k][0] = make_float2(c, c);
      g_Upk[k][1] = make_float2(s, -s);
    } else {
      float c = e[0].x, s = e[2].x;
      g_Upk[k][0] = make_float2(c, c);
      g_Upk[k][1] = make_float2(-s, -s);
      g_Upk[k][2] = make_float2(s, s);
    }
  }
}

// Apply one wire (local reg-bit K) of type T (0=RX,1=RY,2=GEN) to NA amplitudes.
template<int NA, int K, int T>
__device__ __forceinline__ void wireOp(u64* v, const float2* Ug) {
  const u64* U = (const u64*)Ug;
  if (T == 0) {           // RX: nA = c*A + (s,-s)*swap(B); nB = c*B + (s,-s)*swap(A)
    u64 c = U[0], s = U[1];
#pragma unroll
    for (int j = 0; j < NA; j++) if (!((j >> K) & 1)) {
      u64 A = v[j], B = v[j | (1 << K)];
      v[j]            = f2fma(s, swp(B), f2mul(c, A));
      v[j | (1 << K)] = f2fma(s, swp(A), f2mul(c, B));
    }
  } else if (T == 1) {    // RY: nA = c*A - s*B; nB = s*A + c*B
    u64 c = U[0], ns = U[1], s = U[2];
#pragma unroll
    for (int j = 0; j < NA; j++) if (!((j >> K) & 1)) {
      u64 A = v[j], B = v[j | (1 << K)];
      v[j]            = f2fma(ns, B, f2mul(c, A));
      v[j | (1 << K)] = f2fma(c, B, f2mul(s, A));
    }
  } else {                // general complex 2x2
    u64 u0 = U[0], u1 = U[1], u2 = U[2], u3 = U[3];
    u64 u4 = U[4], u5 = U[5], u6 = U[6], u7 = U[7];
#pragma unroll
    for (int j = 0; j < NA; j++) if (!((j >> K) & 1)) {
      u64 A = v[j], B = v[j | (1 << K)];
      u64 As = swp(A), Bs = swp(B);
      u64 nA = f2mul(u0, A);
      nA = f2fma(u1, As, nA); nA = f2fma(u2, B, nA); nA = f2fma(u3, Bs, nA);
      u64 nB = f2mul(u4, A);
      nB = f2fma(u5, As, nB); nB = f2fma(u6, B, nB); nB = f2fma(u7, Bs, nB);
      v[j] = nA; v[j | (1 << K)] = nB;
    }
  }
}

// Typed static sweep: NW wires on compile-time masks (ascending), types T0..T3.
template<int NTT, int NW, int M0, int M1, int M2, int M3, int T0, int T1, int T2, int T3>
__device__ __forceinline__ void usweepT(float2* t, int ubase) {
  constexpr int NA = 1 << NW;
  constexpr int ITERS = (TILE >> NW) / NTT;
  __syncthreads();
#pragma unroll
  for (int it = 0; it < ITERS; it++) {
    int q = threadIdx.x + it * NTT;
    int idx = q;
    idx = ((idx & ~(M0 - 1)) << 1) | (idx & (M0 - 1));
    if (NW > 1) idx = ((idx & ~(M1 - 1)) << 1) | (idx & (M1 - 1));
    if (NW > 2) idx = ((idx & ~(M2 - 1)) << 1) | (idx & (M2 - 1));
    if (NW > 3) idx = ((idx & ~(M3 - 1)) << 1) | (idx & (M3 - 1));
    const int MS[4] = {M0, M1, M2, M3};
    u64 v[NA];
#pragma unroll
    for (int j = 0; j < NA; j++) {
      int off = 0;
#pragma unroll
      for (int k = 0; k < 4; k++) if (k < NW && ((j >> k) & 1)) off |= MS[k];
      v[j] = *(const u64*)&t[sw(idx | off)];
    }
    wireOp<NA, 0, T0>(v, g_Upk[ubase + 0]);
    if (NW > 1) wireOp<NA, 1, T1>(v, g_Upk[ubase + 1]);
    if (NW > 2) wireOp<NA, 2, T2>(v, g_Upk[ubase + 2]);
    if (NW > 3) wireOp<NA, 3, T3>(v, g_Upk[ubase + 3]);
#pragma unroll
    for (int j = 0; j < NA; j++) {
      int off = 0;
#pragma unroll
      for (int k = 0; k < 4; k++) if (k < NW && ((j >> k) & 1)) off |= MS[k];
      *(u64*)&t[sw(idx | off)] = v[j];
    }
  }
}

// CNOT-chain permutation sweep.
template<bool ASC, int NTT>
__device__ __forceinline__ void permchain(float2* t) {
  __syncthreads();
  constexpr int PER = TILE / NTT;
  float2 v[PER];
  int d0 = threadIdx.x * PER;
#pragma unroll
  for (int j = 0; j < PER; j++) {
    int d = d0 + j, src;
    if (ASC) {
      src = d;
#pragma unroll
      for (int k = 9; k >= 4; k--) src ^= (src >> 1) & (1 << k);
    } else {
      src = d ^ ((d >> 1) & 0x0FFF);
    }
    v[j] = t[sw(src)];
  }
  __syncthreads();
#pragma unroll
  for (int j = 0; j < PER; j++) t[sw(d0 + j)] = v[j];
}

// ---- global <-> smem tile movement (smem swizzled) ----
__device__ __forceinline__ void loadA(float2* t, int b, int o) {
  const float4* gp = (const float4*)(g_psi + (long long)b * DIM + o * TILE);
  for (int k = threadIdx.x; k < TILE / 2; k += blockDim.x) {
    float4 w4 = gp[k];
    t[sw(2 * k)]     = make_float2(w4.x, w4.y);
    t[sw(2 * k + 1)] = make_float2(w4.z, w4.w);
  }
}
__device__ __forceinline__ void storeA(const float2* t, int b, int o) {
  float4* gp = (float4*)(g_psi + (long long)b * DIM + o * TILE);
  for (int k = threadIdx.x; k < TILE / 2; k += blockDim.x) {
    float2 a = t[sw(2 * k)], c = t[sw(2 * k + 1)];
    gp[k] = make_float4(a.x, a.y, c.x, c.y);
  }
}
__device__ __forceinline__ void loadB(float2* t, int b, int o, int lead) {
  const float2* base = g_psi + (long long)b * DIM + (o << 10);
  for (int k = threadIdx.x; k < TILE / 2; k += blockDim.x) {
    int s = 2 * k;
    int r = s >> 10, lo = s & 1023;
    float4 w4 = *(const float4*)(base + (r << 12) + lo);
    t[sw(s)] = make_float2(w4.x, w4.y);
    int d1 = (s + 1) ^ (lead << 13);
    t[sw(d1)] = make_float2(w4.z, w4.w);
  }
}
__device__ __forceinline__ void storeB(const float2* t, int b, int o, int foldmask) {
  float2* base = g_psi + (long long)b * DIM + (o << 10);
  for (int k = threadIdx.x; k < TILE / 2; k += blockDim.x) {
    int d = 2 * k;
    int src = d ^ ((d >> 1) & foldmask);
    float2 a = t[sw(src)], c = t[sw(src + 1)];
    int r = d >> 10, lo = d & 1023;
    *(float4*)(base + (r << 12) + lo) = make_float4(a.x, a.y, c.x, c.y);
  }
}

// ---- kernels ----
__global__ void __launch_bounds__(256) kNorm(const float* states) {
  __shared__ float red[256];
  int b = blockIdx.x;
  const float4* p = (const float4*)(states + (long long)b * DIM);
  float s = 0.f;
  for (int k = threadIdx.x; k < DIM / 4; k += 256) {
    float4 v = p[k];
    s += v.x * v.x + v.y * v.y + v.z * v.z + v.w * v.w;
  }
  red[threadIdx.x] = s;
  __syncthreads();
  for (int off = 128; off; off >>= 1) {
    if (threadIdx.x < off) red[threadIdx.x] += red[threadIdx.x + off];
    __syncthreads();
  }
  if (threadIdx.x == 0) g_norminv[b] = rsqrtf(red[0]);
}

__global__ void __launch_bounds__(NTP) kP1(const float* states) {
  extern __shared__ float2 t[];
  int b = blockIdx.x >> 2, o = blockIdx.x & 3;
  float ninv = g_norminv[b];
  const float4* gp = (const float4*)(states + (long long)b * DIM + o * TILE);
  for (int k = threadIdx.x; k < TILE / 4; k += NTP) {
    float4 v = gp[k];
    int i = 4 * k;
    t[sw(i + 0)] = make_float2(v.x * ninv, 0.f);
    t[sw(i + 1)] = make_float2(v.y * ninv, 0.f);
    t[sw(i + 2)] = make_float2(v.z * ninv, 0.f);
    t[sw(i + 3)] = make_float2(v.w * ninv, 0.f);
  }
  usweepT<NTP, 4, 1, 2, 4, 8,           2, 0, 0, 0>(t, 0);
  usweepT<NTP, 4, 1024, 2048, 4096, 8192, 1, 1, 1, 1>(t, 4);
  permchain<true, NTP>(t);
  usweepT<NTP, 2, 16, 32, 64, 128,      0, 0, 0, 0>(t, 8);
  __syncthreads();
  storeA(t, b, o);
}

__global__ void __launch_bounds__(NTP) kP2() {
  extern __shared__ float2 t[];
  int b = blockIdx.x >> 2, o = blockIdx.x & 3;
  loadB(t, b, o, 0);
  usweepT<NTP, 4, 1, 2, 4, 8,             0, 0, 0, 0>(t, 10);
  usweepT<NTP, 4, 16, 32, 64, 128,        0, 0, 0, 0>(t, 14);
  usweepT<NTP, 4, 256, 512, 1024, 2048,   0, 0, 0, 0>(t, 18);
  usweepT<NTP, 2, 4096, 8192, 0x4000, 0x8000, 2, 2, 0, 0>(t, 22);
  __syncthreads();
  storeB(t, b, o, 0x1C00);
}

__global__ void __launch_bounds__(NTP) kP3() {
  extern __shared__ float2 t[];
  int b = blockIdx.x >> 2, o = blockIdx.x & 3;
  loadA(t, b, o);
  usweepT<NTP, 2, 1024, 2048, 0x4000, 0x8000, 0, 0, 0, 0>(t, 24);
  permchain<false, NTP>(t);
  usweepT<NTP, 4, 2, 4, 8, 16,            1, 1, 1, 1>(t, 26);
  usweepT<NTP, 4, 32, 64, 128, 256,       1, 1, 1, 1>(t, 30);
  usweepT<NTP, 4, 512, 1024, 2048, 4096,  1, 1, 1, 1>(t, 34);
  usweepT<NTP, 1, 8192, 0x4000, 0x8000, 0x10000, 1, 1, 1, 1>(t, 38);
  __syncthreads();
  storeA(t, b, o);
}

__global__ void __launch_bounds__(NTP) kP4() {
  extern __shared__ float2 t[];
  int b = blockIdx.x >> 2, o = blockIdx.x & 3;
  loadB(t, b, o, 1);
  usweepT<NTP, 4, 2, 4, 8, 16,            0, 0, 0, 0>(t, 39);
  usweepT<NTP, 4, 32, 64, 128, 256,       0, 0, 0, 0>(t, 43);
  usweepT<NTP, 4, 512, 1024, 2048, 4096,  0, 0, 0, 2>(t, 47);
  usweepT<NTP, 2, 1, 8192, 0x4000, 0x8000, 2, 2, 0, 0>(t, 51);
  __syncthreads();
  storeB(t, b, o, 0x1C00);
}

// Measure: cross-tile X (pre-P5, commutes), P5 in smem, then WHT-based Z + packed X.
__global__ void __launch_bounds__(NTM) kMeasure() {
  extern __shared__ float2 t[];
  int b = blockIdx.x >> 2, o = blockIdx.x & 3;
  loadA(t, b, o);
  __syncthreads();

  float zacc[16], xacc[16];
#pragma unroll
  for (int w = 0; w < 16; ++w) { zacc[w] = 0.f; xacc[w] = 0.f; }

  const float2* base = g_psi + (long long)b * DIM;
  if (o < 2) {      // bit15==0: Xop_0 = X_b15 ; Xop_15 = X_b15 X_b0
    float a0 = 0.f, a15 = 0.f;
    for (int l = threadIdx.x; l < TILE; l += NTM) {
      int i = (o << 14) | l;
      float2 a = t[sw(l)];
      float2 p0 = base[i | 0x8000];
      float2 p1 = base[(i | 0x8000) ^ 1];
      a0 += a.x * p0.x + a.y * p0.y;
      a15 += a.x * p1.x + a.y * p1.y;
    }
    xacc[0] = 2.f * a0;
    xacc[15] = 2.f * a15;
  }
  if ((o & 1) == 0) {  // bit14==0: Xop_1 = X_b14
    float a1 = 0.f;
    for (int l = threadIdx.x; l < TILE; l += NTM) {
      int i = (o << 14) | l;
      float2 a = t[sw(l)];
      float2 p = base[i | 0x4000];
      a1 += a.x * p.x + a.y * p.y;
    }
    xacc[1] = 2.f * a1;
  }

  // P5: RX b10,b11 + 12-CNOT ladder
  usweepT<NTM, 2, 1024, 2048, 0x4000, 0x8000, 0, 0, 0, 0>(t, 53);
  permchain<false, NTM>(t);
  __syncthreads();

  // Pass A: bits {1..4}. X for w=14..11 + ALL Z via 4-level WHT of |a|^2.
  u64 zD[4] = {0, 0, 0, 0};       // D_k -> zacc[14-k]
  u64 zS1 = 0;                    // unsigned S   -> zacc[1] (block-const sign)
  u64 z15 = 0;                    // bit0-signed  -> zacc[15]; zacc[0] = +/- same
  u64 zB[9] = {0,0,0,0,0,0,0,0,0};// idx-bit-signed -> zacc[2..10]
  u64 xA[4] = {0, 0, 0, 0};
  for (int q = threadIdx.x; q < TILE / 16; q += NTM) {
    int idx = (q & 1) | ((q & ~1) << 4);
    u64 V[16];
#pragma unroll
    for (int j = 0; j < 16; j++) V[j] = *(const u64*)&t[sw(idx | (j << 1))];
#pragma unroll
    for (int k = 0; k < 4; k++)
#pragma unroll
      for (int j = 0; j < 16; j++) if (!((j >> k) & 1))
        xA[k] = f2fma(V[j], V[j | (1 << k)], xA[k]);
    // |a|^2 per lane, then WHT
#pragma unroll
    for (int j = 0; j < 16; j++) V[j] = f2mul(V[j], V[j]);
    u64 A0 = f2add(V[0], V[1]),  B0 = f2sub(V[0], V[1]);
    u64 A1 = f2add(V[2], V[3]),  B1 = f2sub(V[2], V[3]);
    u64 A2 = f2add(V[4], V[5]),  B2 = f2sub(V[4], V[5]);
    u64 A3 = f2add(V[6], V[7]),  B3 = f2sub(V[6], V[7]);
    u64 A4 = f2add(V[8], V[9]),  B4 = f2sub(V[8], V[9]);
    u64 A5 = f2add(V[10], V[11]), B5 = f2sub(V[10], V[11]);
    u64 A6 = f2add(V[12], V[13]), B6 = f2sub(V[12], V[13]);
    u64 A7 = f2add(V[14], V[15]), B7 = f2sub(V[14], V[15]);
    u64 D0 = f2add(f2add(f2add(B0, B1), f2add(B2, B3)),
                   f2add(f2add(B4, B5), f2add(B6, B7)));
    u64 C0 = f2add(A0, A1), E0 = f2sub(A0, A1);
    u64 C1 = f2add(A2, A3), E1 = f2sub(A2, A3);
    u64 C2 = f2add(A4, A5), E2 = f2sub(A4, A5);
    u64 C3 = f2add(A6, A7), E3 = f2sub(A6, A7);
    u64 D1 = f2add(f2add(E0, E1), f2add(E2, E3));
    u64 F0 = f2add(C0, C1), G0 = f2sub(C0, C1);
    u64 F1 = f2add(C2, C3), G1 = f2sub(C2, C3);
    u64 D2 = f2add(G0, G1);
    u64 S  = f2add(F0, F1);
    u64 D3 = f2sub(F0, F1);
    zD[0] = f2add(zD[0], D0); zD[1] = f2add(zD[1], D1);
    zD[2] = f2add(zD[2], D2); zD[3] = f2add(zD[3], D3);
    zS1 = f2add(zS1, S);
    u64 Sn = f2mul(0xBF800000BF800000ULL, S);
    z15 = f2add(z15, (idx & 1) ? Sn : S);
#pragma unroll
    for (int w = 2; w <= 10; w++)
      zB[w - 2] = f2add(zB[w - 2], ((idx >> (15 - w)) & 1) ? Sn : S);
  }
#pragma unroll
  for (int k = 0; k < 4; k++) { zacc[14 - k] = lsum(zD[k]); xacc[14 - k] = 2.f * lsum(xA[k]); }
  zacc[15] = lsum(z15);
  zacc[0]  = ((o >> 1) & 1) ? -zacc[15] : zacc[15];
  zacc[1]  = (o & 1) ? -lsum(zS1) : lsum(zS1);
#pragma unroll
  for (int w = 2; w <= 10; w++) zacc[w] = lsum(zB[w - 2]);

  // Pass B: bits {5..8} -> X for w=10..7
  {
    u64 xB[4] = {0, 0, 0, 0};
    for (int q = threadIdx.x; q < TILE / 16; q += NTM) {
      int idx = (q & 31) | ((q & ~31) << 4);
      u64 V[16];
#pragma unroll
      for (int j = 0; j < 16; j++) V[j] = *(const u64*)&t[sw(idx | (j << 5))];
#pragma unroll
      for (int k = 0; k < 4; k++)
#pragma unroll
        for (int j = 0; j < 16; j++) if (!((j >> k) & 1))
          xB[k] = f2fma(V[j], V[j | (1 << k)], xB[k]);
    }
#pragma unroll
    for (int k = 0; k < 4; k++) xacc[10 - k] = 2.f * lsum(xB[k]);
  }
  // Pass C: bits {9..12} -> X for w=6..3
  {
    u64 xC[4] = {0, 0, 0, 0};
    for (int q = threadIdx.x; q < TILE / 16; q += NTM) {
      int idx = (q & 511) | ((q & ~511) << 4);
      u64 V[16];
#pragma unroll
      for (int j = 0; j < 16; j++) V[j] = *(const u64*)&t[sw(idx | (j << 9))];
#pragma unroll
      for (int k = 0; k < 4; k++)
#pragma unroll
        for (int j = 0; j < 16; j++) if (!((j >> k) & 1))
          xC[k] = f2fma(V[j], V[j | (1 << k)], xC[k]);
    }
#pragma unroll
    for (int k = 0; k < 4; k++) xacc[6 - k] = 2.f * lsum(xC[k]);
  }
  // Pass D: mask 8192 -> w=2
  {
    u64 xD = 0;
    for (int q = threadIdx.x; q < TILE / 2; q += NTM)
      xD = f2fma(*(const u64*)&t[sw(q)], *(const u64*)&t[sw(q | 8192)], xD);
    xacc[2] = 2.f * lsum(xD);
  }

  __syncthreads();
  float* red = (float*)t;
  int lane = threadIdx.x & 31, wid = threadIdx.x >> 5;
#pragma unroll
  for (int v = 0; v < 32; ++v) {
    float val = (v < 16) ? zacc[v] : xacc[v - 16];
#pragma unroll
    for (int off = 16; off; off >>= 1) val += __shfl_down_sync(0xffffffffu, val, off);
    if (lane == 0) red[wid * 32 + v] = val;
  }
  __syncthreads();
  if (threadIdx.x < 32) {
    int v = threadIdx.x;
    float s = 0.f;
    for (int w = 0; w < NTM / 32; ++w) s += red[w * 32 + v];
    g_part[blockIdx.x * 32 + v] = s;
  }
}

__global__ void __launch_bounds__(128) kHead(
    const float* theta_ry, const float* w1, const float* b1,
    const float* w2, const float* b2, const float* g1, const float* be1,
    const float* g2, const float* be2, const float* wh, const float* bh,
    float* out) {
  int b = blockIdx.x * blockDim.x + threadIdx.x;
  if (b >= BSZ) return;

  float attn[16], xs[16];
#pragma unroll
  for (int w = 0; w < 16; ++w) {
    float za = 0.f, xa = 0.f;
#pragma unroll
    for (int o = 0; o < 4; ++o) {
      za += g_part[(b * 4 + o) * 32 + w];
      xa += g_part[(b * 4 + o) * 32 + 16 + w];
    }
    attn[w] = za; xs[w] = xa;
  }
  float th = theta_ry[1];
  float cb = cosf(th), sb = sinf(th);
  float m[16];
#pragma unroll
  for (int w = 0; w < 16; ++w) m[w] = cb * attn[w] - sb * xs[w];

  float mu = 0.f;
#pragma unroll
  for (int w = 0; w < 16; ++w) mu += attn[w];
  mu *= (1.f / 16.f);
  float var = 0.f;
#pragma unroll
  for (int w = 0; w < 16; ++w) { float d = attn[w] - mu; var += d * d; }
  var *= (1.f / 16.f);
  float rs = rsqrtf(var + 1e-5f);
  float x[16];
#pragma unroll
  for (int w = 0; w < 16; ++w) x[w] = (attn[w] - mu) * rs * g1[16 + w] + be1[16 + w];

  float ffn[16];
#pragma unroll
  for (int w = 0; w < 16; ++w) ffn[w] = b2[16 + w];
  for (int j = 0; j < 64; ++j) {
    float h = b1[64 + j];
#pragma unroll
    for (int w = 0; w < 16; ++w) h += m[w] * w1[1024 + j * 16 + w];
    h = fmaxf(h, 0.f);
#pragma unroll
    for (int w = 0; w < 16; ++w) ffn[w] += h * w2[1024 + w * 64 + j];
  }

  float y[16];
#pragma unroll
  for (int w = 0; w < 16; ++w) y[w] = x[w] + ffn[w];
  float mu2 = 0.f;
#pragma unroll
  for (int w = 0; w < 16; ++w) mu2 += y[w];
  mu2 *= (1.f / 16.f);
  float var2 = 0.f;
#pragma unroll
  for (int w = 0; w < 16; ++w) { float d = y[w] - mu2; var2 += d * d; }
  var2 *= (1.f / 16.f);
  float rs2 = rsqrtf(var2 + 1e-5f);

  float ov = bh[0];
#pragma unroll
  for (int w = 0; w < 16; ++w)
    ov += ((y[w] - mu2) * rs2 * g2[16 + w] + be2[16 + w]) * wh[w];
  out[b] = ov;
}

extern "C" void kernel_launch(void* const* d_in, const int* in_sizes, int n_in,
                              void* d_out, int out_size) {
  const float* states = (const float*)d_in[0];
  const float* ra     = (const float*)d_in[1];
  const float* trx    = (const float*)d_in[2];
  const float* try_   = (const float*)d_in[3];
  const float* w1     = (const float*)d_in[4];
  const float* b1     = (const float*)d_in[5];
  const float* w2     = (const float*)d_in[6];
  const float* b2     = (const float*)d_in[7];
  const float* g1     = (const float*)d_in[8];
  const float* be1    = (const float*)d_in[9];
  const float* g2     = (const float*)d_in[10];
  const float* be2    = (const float*)d_in[11];
  const float* wh     = (const float*)d_in[12];
  const float* bh     = (const float*)d_in[13];
  float* out = (float*)d_out;

  cudaFuncSetAttribute(kP1, cudaFuncAttributeMaxDynamicSharedMemorySize, SMEM_BYTES);
  cudaFuncSetAttribute(kP2, cudaFuncAttributeMaxDynamicSharedMemorySize, SMEM_BYTES);
  cudaFuncSetAttribute(kP3, cudaFuncAttributeMaxDynamicSharedMemorySize, SMEM_BYTES);
  cudaFuncSetAttribute(kP4, cudaFuncAttributeMaxDynamicSharedMemorySize, SMEM_BYTES);
  cudaFuncSetAttribute(kMeasure, cudaFuncAttributeMaxDynamicSharedMemorySize, SMEM_BYTES);

  kSetup<<<1, 32>>>(ra, trx, try_);
  kNorm<<<BSZ, 256>>>(states);
  kP1<<<BSZ * 4, NTP, SMEM_BYTES>>>(states);
  kP2<<<BSZ * 4, NTP, SMEM_BYTES>>>();
  kP3<<<BSZ * 4, NTP, SMEM_BYTES>>>();
  kP4<<<BSZ * 4, NTP, SMEM_BYTES>>>();
  kMeasure<<<BSZ * 4, NTM, SMEM_BYTES>>>();
  kHead<<<(BSZ + 127) / 128, 128>>>(try_, w1, b1, w2, b2, g1, be1, g2, be2, wh, bh, out);
}